// round 1
// baseline (speedup 1.0000x reference)
#include <cuda_runtime.h>
#include <cuda_bf16.h>

// ---------------------------------------------------------------------------
// SelfAttention: B=8, T=2048, C=512, H=4 (each head uses full C=512)
//   qkv  = x @ qkv_w^T              [16384, 6144]
//   S    = scale * Q K^T  (per b,h) [2048, 2048] x32
//   P    = softmax(S, axis=-1)
//   O    = P V            (per b,h) [2048, 512]  x32  -> packed [16384, 2048]
//   out  = O @ proj_w^T + proj_b    [16384, 512]
// Baseline: fp32 tiled SGEMM (128x128x16, 8x8/thread), fp32-exact vs reference.
// ---------------------------------------------------------------------------

#define BM 128
#define BN 128
#define BK 16

// Scratch (allocation-free rule: device globals)
__device__ float g_qkv [100663296ULL]; // 8*2048*6144   (402 MB)
__device__ float g_attn[134217728ULL]; // 32*2048*2048  (537 MB)
__device__ float g_ao  [ 33554432ULL]; // 8*2048*2048   (134 MB)

template<bool TRANS_B, bool ADD_BIAS>
__global__ __launch_bounds__(256, 2)
void sgemm_kernel(const float* __restrict__ Ag, const float* __restrict__ Bg,
                  float* __restrict__ Cg, const float* __restrict__ bias,
                  int K, int lda, int ldb, int ldc,
                  int zdiv,
                  long long sA1, long long sA2,
                  long long sB1, long long sB2,
                  long long sC1, long long sC2,
                  float alpha)
{
    __shared__ float As[BK][BM];
    __shared__ float Bs[BK][BN];

    const int z  = blockIdx.z;
    const int zq = z / zdiv;
    const int zr = z - zq * zdiv;

    const float* A = Ag + zq * sA1 + zr * sA2 + (long long)blockIdx.y * BM * lda;
    const float* B = Bg + zq * sB1 + zr * sB2;
    if (TRANS_B) B += (long long)blockIdx.x * BN * ldb;
    else         B += blockIdx.x * BN;
    float* C = Cg + zq * sC1 + zr * sC2
                  + (long long)blockIdx.y * BM * ldc + blockIdx.x * BN;

    const int tid  = threadIdx.x;
    const int arow = tid >> 2;          // 0..63
    const int acol = (tid & 3) << 2;    // 0,4,8,12
    const int tx   = tid & 15;
    const int ty   = tid >> 4;

    float acc[8][8];
#pragma unroll
    for (int i = 0; i < 8; i++)
#pragma unroll
        for (int j = 0; j < 8; j++) acc[i][j] = 0.f;

    for (int k0 = 0; k0 < K; k0 += BK) {
        // ---- load A tile (row-major [M,K]) transposed into As[k][m]
#pragma unroll
        for (int i = 0; i < 2; i++) {
            const int r = arow + i * 64;
            float4 v = *(const float4*)(A + (long long)r * lda + k0 + acol);
            As[acol + 0][r] = v.x;
            As[acol + 1][r] = v.y;
            As[acol + 2][r] = v.z;
            As[acol + 3][r] = v.w;
        }
        // ---- load B tile
        if (TRANS_B) {       // B is [N,K]: Bs[k][n] = B[n*ldb + k]
#pragma unroll
            for (int i = 0; i < 2; i++) {
                const int r = arow + i * 64;
                float4 v = *(const float4*)(B + (long long)r * ldb + k0 + acol);
                Bs[acol + 0][r] = v.x;
                Bs[acol + 1][r] = v.y;
                Bs[acol + 2][r] = v.z;
                Bs[acol + 3][r] = v.w;
            }
        } else {             // B is [K,N]: Bs[k][n] = B[k*ldb + n]
#pragma unroll
            for (int i = 0; i < 2; i++) {
                const int kr = (tid >> 5) + i * 8;   // 0..15
                const int nc = (tid & 31) << 2;      // 0..124
                float4 v = *(const float4*)(B + (long long)(k0 + kr) * ldb + nc);
                *(float4*)&Bs[kr][nc] = v;
            }
        }
        __syncthreads();

#pragma unroll
        for (int k = 0; k < BK; k++) {
            float a[8], b[8];
            *(float4*)&a[0] = *(const float4*)&As[k][ty * 4];
            *(float4*)&a[4] = *(const float4*)&As[k][64 + ty * 4];
            *(float4*)&b[0] = *(const float4*)&Bs[k][tx * 4];
            *(float4*)&b[4] = *(const float4*)&Bs[k][64 + tx * 4];
#pragma unroll
            for (int i = 0; i < 8; i++)
#pragma unroll
                for (int j = 0; j < 8; j++)
                    acc[i][j] += a[i] * b[j];
        }
        __syncthreads();
    }

    // ---- epilogue
#pragma unroll
    for (int i = 0; i < 8; i++) {
        const int r = (i < 4) ? (ty * 4 + i) : (64 + ty * 4 + (i - 4));
#pragma unroll
        for (int jh = 0; jh < 2; jh++) {
            const int c = jh ? (64 + tx * 4) : (tx * 4);
            float4 v;
            v.x = acc[i][jh * 4 + 0] * alpha;
            v.y = acc[i][jh * 4 + 1] * alpha;
            v.z = acc[i][jh * 4 + 2] * alpha;
            v.w = acc[i][jh * 4 + 3] * alpha;
            if (ADD_BIAS) {
                const int gb = blockIdx.x * BN + c;
                v.x += bias[gb + 0];
                v.y += bias[gb + 1];
                v.z += bias[gb + 2];
                v.w += bias[gb + 3];
            }
            *(float4*)(C + (long long)r * ldc + c) = v;
        }
    }
}

// Row softmax over S[rows, 2048]; one 256-thread block per row, 8 elems/thread.
__global__ __launch_bounds__(256)
void softmax_kernel(float* __restrict__ S)
{
    const int T = 2048;
    float* row = S + (long long)blockIdx.x * T;
    const int tid = threadIdx.x;

    float4 v0 = *(const float4*)(row + tid * 8);
    float4 v1 = *(const float4*)(row + tid * 8 + 4);

    float m = fmaxf(fmaxf(fmaxf(v0.x, v0.y), fmaxf(v0.z, v0.w)),
                    fmaxf(fmaxf(v1.x, v1.y), fmaxf(v1.z, v1.w)));
#pragma unroll
    for (int o = 16; o; o >>= 1) m = fmaxf(m, __shfl_xor_sync(0xffffffffu, m, o));

    __shared__ float red[8];
    if ((tid & 31) == 0) red[tid >> 5] = m;
    __syncthreads();
    m = red[0];
#pragma unroll
    for (int i = 1; i < 8; i++) m = fmaxf(m, red[i]);

    v0.x = __expf(v0.x - m); v0.y = __expf(v0.y - m);
    v0.z = __expf(v0.z - m); v0.w = __expf(v0.w - m);
    v1.x = __expf(v1.x - m); v1.y = __expf(v1.y - m);
    v1.z = __expf(v1.z - m); v1.w = __expf(v1.w - m);

    float s = v0.x + v0.y + v0.z + v0.w + v1.x + v1.y + v1.z + v1.w;
#pragma unroll
    for (int o = 16; o; o >>= 1) s += __shfl_xor_sync(0xffffffffu, s, o);

    __syncthreads();                 // red reuse
    if ((tid & 31) == 0) red[tid >> 5] = s;
    __syncthreads();
    s = red[0];
#pragma unroll
    for (int i = 1; i < 8; i++) s += red[i];

    const float inv = 1.f / s;
    v0.x *= inv; v0.y *= inv; v0.z *= inv; v0.w *= inv;
    v1.x *= inv; v1.y *= inv; v1.z *= inv; v1.w *= inv;

    *(float4*)(row + tid * 8)     = v0;
    *(float4*)(row + tid * 8 + 4) = v1;
}

extern "C" void kernel_launch(void* const* d_in, const int* in_sizes, int n_in,
                              void* d_out, int out_size)
{
    const float* x      = (const float*)d_in[0];   // [8,2048,512]
    const float* qkv_w  = (const float*)d_in[1];   // [6144,512]
    const float* proj_w = (const float*)d_in[2];   // [512,2048]
    const float* proj_b = (const float*)d_in[3];   // [512]
    float* out = (float*)d_out;                    // [8,2048,512]

    float *qkv, *attn, *ao;
    cudaGetSymbolAddress((void**)&qkv,  g_qkv);
    cudaGetSymbolAddress((void**)&attn, g_attn);
    cudaGetSymbolAddress((void**)&ao,   g_ao);

    const int Bb = 8, T = 2048, H = 4;
    const int BT = Bb * T;                       // 16384
    const float scale = 0.088388347648318447f;   // (512/4)^-0.5

    // 1) QKV projection: [16384,6144] = x[16384,512] @ qkv_w^T
    {
        dim3 grid(6144 / BN, BT / BM, 1);
        sgemm_kernel<true, false><<<grid, 256>>>(
            x, qkv_w, qkv, nullptr,
            512, 512, 512, 6144,
            1, 0, 0, 0, 0, 0, 0, 1.0f);
    }
    // 2) S = scale * Q K^T, batched z = b*H + h
    {
        dim3 grid(T / BN, T / BM, Bb * H);
        sgemm_kernel<true, false><<<grid, 256>>>(
            qkv, qkv + 2048, attn, nullptr,
            512, 6144, 6144, T,
            H,
            (long long)T * 6144, 512,     // A (Q): per-b, per-h
            (long long)T * 6144, 512,     // B (K)
            (long long)H * T * T, (long long)T * T,  // C (S)
            scale);
    }
    // 3) softmax rows
    softmax_kernel<<<Bb * H * T, 256>>>(attn);
    // 4) O = P V, batched; packed into ao[(b*T+q)*2048 + h*512 + c]
    {
        dim3 grid(512 / BN, T / BM, Bb * H);
        sgemm_kernel<false, false><<<grid, 256>>>(
            attn, qkv + 4096, ao, nullptr,
            T, T, 6144, 2048,
            H,
            (long long)H * T * T, (long long)T * T,  // A (P)
            (long long)T * 6144, 512,                // B (V)
            (long long)T * 2048, 512,                // C (O packed)
            1.0f);
    }
    // 5) out = ao @ proj_w^T + proj_b
    {
        dim3 grid(512 / BN, BT / BM, 1);
        sgemm_kernel<true, true><<<grid, 256>>>(
            ao, proj_w, out, proj_b,
            2048, 2048, 2048, 512,
            1, 0, 0, 0, 0, 0, 0, 1.0f);
    }
}

// round 8
// speedup vs baseline: 1.9147x; 1.9147x over previous
#include <cuda_runtime.h>
#include <cuda_bf16.h>
#include <cstdint>

// ---------------------------------------------------------------------------
// SelfAttention B=8,T=2048,C=512,H=4 — split-bf16 (3x) GEMM via mma.sync HMMA
// (tcgen05 is unavailable: harness PTX target is sm_103 without 'a' suffix)
//
// Split trick folded into K: A_ext = [Ahi | Alo | Ahi], B_ext = [Bhi | Bhi | Blo]
// => plain K=96 bf16 GEMM == AhiBhi + AloBhi + AhiBlo  (fp32 accumulate)
// ---------------------------------------------------------------------------

__device__ float g_qkv [100663296ULL]; // [8*2048, 6144]
__device__ float g_attn[134217728ULL]; // [32, 2048, 2048]
__device__ float g_vt  [ 33554432ULL]; // [32, 512, 2048]  (V transposed)
__device__ float g_ao  [ 33554432ULL]; // [8*2048, 2048]

#define KC   32          // fp32 K per stage
#define SA   104         // bf16 row stride (96 data + 8 pad) -> 208B, conflict-free
#define MAT_BYTES (128 * SA * 2)          // 26624 per matrix
#define STAGE_BYTES (2 * MAT_BYTES)       // A + B = 53248
#define SMEM_TOTAL  (2 * STAGE_BYTES)     // double buffer = 106496 (2 CTAs/SM)

__device__ __forceinline__ uint32_t smem_u32(const void* p) {
    uint32_t a;
    asm("{ .reg .u64 t; cvta.to.shared.u64 t, %1; cvt.u32.u64 %0, t; }"
        : "=r"(a) : "l"(p));
    return a;
}

__device__ __forceinline__ void ldsm4(uint32_t* r, uint32_t addr) {
    asm volatile("ldmatrix.sync.aligned.m8n8.x4.shared.b16 {%0,%1,%2,%3}, [%4];"
                 : "=r"(r[0]), "=r"(r[1]), "=r"(r[2]), "=r"(r[3]) : "r"(addr));
}

__device__ __forceinline__ void mma16816(float* d, const uint32_t* a,
                                         uint32_t b0, uint32_t b1) {
    asm volatile(
        "mma.sync.aligned.m16n8k16.row.col.f32.bf16.bf16.f32 "
        "{%0,%1,%2,%3}, {%4,%5,%6,%7}, {%8,%9}, {%0,%1,%2,%3};"
        : "+f"(d[0]), "+f"(d[1]), "+f"(d[2]), "+f"(d[3])
        : "r"(a[0]), "r"(a[1]), "r"(a[2]), "r"(a[3]), "r"(b0), "r"(b1));
}

// fp32x4 -> packed bf16x4 hi and lo residual
__device__ __forceinline__ void split4(float4 v, uint2& hh, uint2& ll) {
    __nv_bfloat162 h0 = __floats2bfloat162_rn(v.x, v.y);
    __nv_bfloat162 h1 = __floats2bfloat162_rn(v.z, v.w);
    float2 f0 = __bfloat1622float2(h0);
    float2 f1 = __bfloat1622float2(h1);
    __nv_bfloat162 l0 = __floats2bfloat162_rn(v.x - f0.x, v.y - f0.y);
    __nv_bfloat162 l1 = __floats2bfloat162_rn(v.z - f1.x, v.w - f1.y);
    hh.x = *(uint32_t*)&h0; hh.y = *(uint32_t*)&h1;
    ll.x = *(uint32_t*)&l0; ll.y = *(uint32_t*)&l1;
}

// ---------------- HMMA GEMM: C[128x128 tile] = alpha * A @ B^T (+bias) ------
// A [M][K] fp32 row-major (lda), B [N][K] fp32 row-major (ldb), C [M][N] (ldc)
__global__ void __launch_bounds__(256, 2)
hmma_gemm(const float* __restrict__ Ag, const float* __restrict__ Bg,
          float* __restrict__ Cg, const float* __restrict__ bias,
          int K, int lda, int ldb, int ldc, int zdiv,
          long long sA1, long long sA2, long long sB1, long long sB2,
          long long sC1, long long sC2, float alpha)
{
    extern __shared__ __align__(16) char smem[];

    const int tid  = threadIdx.x;
    const int lane = tid & 31;
    const int wid  = tid >> 5;
    const int wm   = (wid & 1) * 64;    // warp row offset (2 rows of 64)
    const int wn   = (wid >> 1) * 32;   // warp col offset (4 cols of 32)

    const int z = blockIdx.z;
    const int zq = z / zdiv, zr = z - zq * zdiv;
    const float* A = Ag + zq * sA1 + zr * sA2 + (long long)blockIdx.y * 128 * lda;
    const float* B = Bg + zq * sB1 + zr * sB2 + (long long)blockIdx.x * 128 * ldb;
    float* C = Cg + zq * sC1 + zr * sC2
                  + (long long)blockIdx.y * 128 * ldc + blockIdx.x * 128;

    float d[4][4][4];
#pragma unroll
    for (int i = 0; i < 4; i++)
#pragma unroll
        for (int j = 0; j < 4; j++)
#pragma unroll
            for (int e = 0; e < 4; e++) d[i][j][e] = 0.f;

    const int nch = K / KC;
    for (int c = 0; c < nch; ++c) {
        char* st = smem + (c & 1) * STAGE_BYTES;
        __nv_bfloat16* As = (__nv_bfloat16*)st;
        __nv_bfloat16* Bs = (__nv_bfloat16*)(st + MAT_BYTES);

        // ---- load + split chunk c: A ext=[hi|lo|hi], B ext=[hi|hi|lo] ----
        const float* Ac = A + c * KC;
        const float* Bc = B + c * KC;
#pragma unroll
        for (int i = 0; i < 4; i++) {
            int lin = i * 256 + tid;
            int row = lin >> 3, c4 = lin & 7;           // 128 rows x 8 float4
            float4 v = *(const float4*)(Ac + (long long)row * lda + (c4 << 2));
            uint2 hh, ll; split4(v, hh, ll);
            __nv_bfloat16* p = As + row * SA + (c4 << 2);
            *(uint2*)(p)      = hh;     // hi at k
            *(uint2*)(p + 32) = ll;     // lo at k+32
            *(uint2*)(p + 64) = hh;     // hi at k+64
        }
#pragma unroll
        for (int i = 0; i < 4; i++) {
            int lin = i * 256 + tid;
            int row = lin >> 3, c4 = lin & 7;
            float4 v = *(const float4*)(Bc + (long long)row * ldb + (c4 << 2));
            uint2 hh, ll; split4(v, hh, ll);
            __nv_bfloat16* p = Bs + row * SA + (c4 << 2);
            *(uint2*)(p)      = hh;     // hi at k
            *(uint2*)(p + 32) = hh;     // hi at k+32
            *(uint2*)(p + 64) = ll;     // lo at k+64
        }
        __syncthreads();

        // ---- compute: K_ext = 96 -> 6 k16 steps ----
        const uint32_t a_base = smem_u32(As);
        const uint32_t b_base = smem_u32(Bs);
#pragma unroll
        for (int ks = 0; ks < 6; ks++) {
            uint32_t af[4][4];
#pragma unroll
            for (int mi = 0; mi < 4; mi++) {
                uint32_t addr = a_base +
                    ((wm + mi * 16 + (lane & 15)) * SA + ks * 16 + (lane >> 4) * 8) * 2;
                ldsm4(af[mi], addr);
            }
            uint32_t bf[4][2];
#pragma unroll
            for (int nb = 0; nb < 2; nb++) {
                uint32_t r[4];
                uint32_t addr = b_base +
                    ((wn + nb * 16 + (lane & 15)) * SA + ks * 16 + (lane >> 4) * 8) * 2;
                ldsm4(r, addr);
                bf[nb * 2 + 0][0] = r[0]; bf[nb * 2 + 0][1] = r[2];
                bf[nb * 2 + 1][0] = r[1]; bf[nb * 2 + 1][1] = r[3];
            }
#pragma unroll
            for (int mi = 0; mi < 4; mi++)
#pragma unroll
                for (int ni = 0; ni < 4; ni++)
                    mma16816(d[mi][ni], af[mi], bf[ni][0], bf[ni][1]);
        }
        __syncthreads();
    }

    // ---- epilogue: frags -> gmem ----
    const int r0 = lane >> 2;          // 0..7
    const int c0 = (lane & 3) << 1;    // 0,2,4,6
#pragma unroll
    for (int mi = 0; mi < 4; mi++) {
#pragma unroll
        for (int ni = 0; ni < 4; ni++) {
            int row = wm + mi * 16 + r0;
            int col = wn + ni * 8 + c0;
            float2 v0, v1;
            v0.x = d[mi][ni][0] * alpha; v0.y = d[mi][ni][1] * alpha;
            v1.x = d[mi][ni][2] * alpha; v1.y = d[mi][ni][3] * alpha;
            if (bias) {
                int gc = blockIdx.x * 128 + col;
                float b0 = bias[gc], b1 = bias[gc + 1];
                v0.x += b0; v0.y += b1;
                v1.x += b0; v1.y += b1;
            }
            *(float2*)(C + (long long)row * ldc + col)       = v0;
            *(float2*)(C + (long long)(row + 8) * ldc + col) = v1;
        }
    }
}

// ---------------- softmax over rows of S[*, 2048] ----------------
__global__ __launch_bounds__(256)
void softmax_kernel(float* __restrict__ S)
{
    const int T = 2048;
    float* row = S + (long long)blockIdx.x * T;
    const int tid = threadIdx.x;

    float4 v0 = *(const float4*)(row + tid * 8);
    float4 v1 = *(const float4*)(row + tid * 8 + 4);

    float m = fmaxf(fmaxf(fmaxf(v0.x, v0.y), fmaxf(v0.z, v0.w)),
                    fmaxf(fmaxf(v1.x, v1.y), fmaxf(v1.z, v1.w)));
#pragma unroll
    for (int o = 16; o; o >>= 1) m = fmaxf(m, __shfl_xor_sync(0xffffffffu, m, o));

    __shared__ float red[8];
    if ((tid & 31) == 0) red[tid >> 5] = m;
    __syncthreads();
    m = red[0];
#pragma unroll
    for (int i = 1; i < 8; i++) m = fmaxf(m, red[i]);

    v0.x = __expf(v0.x - m); v0.y = __expf(v0.y - m);
    v0.z = __expf(v0.z - m); v0.w = __expf(v0.w - m);
    v1.x = __expf(v1.x - m); v1.y = __expf(v1.y - m);
    v1.z = __expf(v1.z - m); v1.w = __expf(v1.w - m);

    float s = v0.x + v0.y + v0.z + v0.w + v1.x + v1.y + v1.z + v1.w;
#pragma unroll
    for (int o = 16; o; o >>= 1) s += __shfl_xor_sync(0xffffffffu, s, o);

    __syncthreads();
    if ((tid & 31) == 0) red[tid >> 5] = s;
    __syncthreads();
    s = red[0];
#pragma unroll
    for (int i = 1; i < 8; i++) s += red[i];

    const float inv = 1.f / s;
    v0.x *= inv; v0.y *= inv; v0.z *= inv; v0.w *= inv;
    v1.x *= inv; v1.y *= inv; v1.z *= inv; v1.w *= inv;

    *(float4*)(row + tid * 8)     = v0;
    *(float4*)(row + tid * 8 + 4) = v1;
}

// ---------------- V transpose: vt[z][c][t] = qkv[b,t, 4096 + h*512 + c] ----
__global__ __launch_bounds__(256)
void transpose_v_kernel(const float* __restrict__ qkv, float* __restrict__ vt)
{
    __shared__ float tile[32][33];
    const int tx = threadIdx.x & 31, ty = threadIdx.x >> 5;  // 32 x 8
    const int z = blockIdx.z, b = z >> 2, h = z & 3;
    const long long srcbase = (long long)b * 2048 * 6144 + 4096 + h * 512;
    const int k0 = blockIdx.x << 5, c0 = blockIdx.y << 5;
#pragma unroll
    for (int i = 0; i < 4; i++)
        tile[ty + i * 8][tx] =
            qkv[srcbase + (long long)(k0 + ty + i * 8) * 6144 + c0 + tx];
    __syncthreads();
    const long long dstbase = (long long)z * 512 * 2048;
#pragma unroll
    for (int i = 0; i < 4; i++)
        vt[dstbase + (long long)(c0 + ty + i * 8) * 2048 + k0 + tx] =
            tile[tx][ty + i * 8];
}

// ---------------------------------------------------------------------------
extern "C" void kernel_launch(void* const* d_in, const int* in_sizes, int n_in,
                              void* d_out, int out_size)
{
    const float* x      = (const float*)d_in[0];   // [8,2048,512]
    const float* qkv_w  = (const float*)d_in[1];   // [6144,512]
    const float* proj_w = (const float*)d_in[2];   // [512,2048]
    const float* proj_b = (const float*)d_in[3];   // [512]
    float* out = (float*)d_out;                    // [8,2048,512]

    float *qkv, *attn, *vt, *ao;
    cudaGetSymbolAddress((void**)&qkv,  g_qkv);
    cudaGetSymbolAddress((void**)&attn, g_attn);
    cudaGetSymbolAddress((void**)&vt,   g_vt);
    cudaGetSymbolAddress((void**)&ao,   g_ao);

    cudaFuncSetAttribute(hmma_gemm, cudaFuncAttributeMaxDynamicSharedMemorySize,
                         SMEM_TOTAL);

    const int T = 2048;
    const float scale = 0.088388347648318447f;   // (512/4)^-0.5
    const long long TT = (long long)T * T;

    // 1) qkv[16384,6144] = x @ qkv_w^T
    {
        dim3 grid(48, 128, 1);
        hmma_gemm<<<grid, 256, SMEM_TOTAL>>>(
            x, qkv_w, qkv, nullptr,
            512, 512, 512, 6144, 1,
            0, 0, 0, 0, 0, 0, 1.0f);
    }
    // 1b) vt[z][c][t] = V
    {
        dim3 grid(64, 16, 32);
        transpose_v_kernel<<<grid, 256>>>(qkv, vt);
    }
    // 2) S = scale * Q K^T   (z = b*4 + h)
    {
        dim3 grid(16, 16, 32);
        hmma_gemm<<<grid, 256, SMEM_TOTAL>>>(
            qkv, qkv + 2048, attn, nullptr,
            512, 6144, 6144, T, 4,
            (long long)T * 6144, 512,
            (long long)T * 6144, 512,
            4 * TT, TT, scale);
    }
    // 3) softmax rows
    softmax_kernel<<<32 * T, 256>>>(attn);
    // 4) O = P V^T(vt)  -> ao packed [b*T + q][h*512 + c]
    {
        dim3 grid(4, 16, 32);
        hmma_gemm<<<grid, 256, SMEM_TOTAL>>>(
            attn, vt, ao, nullptr,
            T, T, T, T, 4,
            4 * TT, TT,
            (long long)4 * 512 * T, (long long)512 * T,
            (long long)T * T, 512, 1.0f);
    }
    // 5) out = ao @ proj_w^T + proj_b
    {
        dim3 grid(4, 128, 1);
        hmma_gemm<<<grid, 256, SMEM_TOTAL>>>(
            ao, proj_w, out, proj_b,
            T, T, T, 512, 1,
            0, 0, 0, 0, 0, 0, 1.0f);
    }
}

// round 12
// speedup vs baseline: 2.1025x; 1.0981x over previous
#include <cuda_runtime.h>
#include <cuda_bf16.h>
#include <cstdint>

// ---------------------------------------------------------------------------
// SelfAttention B=8,T=2048,C=512,H=4 — split-bf16 (3x) GEMM via mma.sync HMMA
// Round 9: operands pre-split to (hi,lo) bf16 in gmem; GEMM uses cp.async
// 3-stage pipeline (no cvt/STS in loop); products: AhBh + AhBl + AlBh.
// ---------------------------------------------------------------------------

__device__ float          g_attn  [134217728ULL]; // [32,2048,2048] fp32 S
__device__ __nv_bfloat16  g_qkv_hi[100663296ULL]; // [16384,6144]
__device__ __nv_bfloat16  g_qkv_lo[100663296ULL];
__device__ __nv_bfloat16  g_p_hi  [134217728ULL]; // softmax(S) split
__device__ __nv_bfloat16  g_p_lo  [134217728ULL];
__device__ __nv_bfloat16  g_vt_hi [ 33554432ULL]; // [32,512,2048]
__device__ __nv_bfloat16  g_vt_lo [ 33554432ULL];
__device__ __nv_bfloat16  g_ao_hi [ 33554432ULL]; // [16384,2048]
__device__ __nv_bfloat16  g_ao_lo [ 33554432ULL];
__device__ __nv_bfloat16  g_x_hi  [  8388608ULL];
__device__ __nv_bfloat16  g_x_lo  [  8388608ULL];
__device__ __nv_bfloat16  g_w1_hi [  3145728ULL]; // qkv_w [6144,512]
__device__ __nv_bfloat16  g_w1_lo [  3145728ULL];
__device__ __nv_bfloat16  g_w2_hi [  1048576ULL]; // proj_w [512,2048]
__device__ __nv_bfloat16  g_w2_lo [  1048576ULL];

#define SA 72                              // bf16 row stride (64 data + 8 pad)
#define MAT_BYTES  (128 * SA * 2)          // 18432
#define STAGE_BYTES (2 * MAT_BYTES)        // 36864
#define SMEM_TOTAL  (3 * STAGE_BYTES)      // 110592 -> 2 CTAs/SM

__device__ __forceinline__ uint32_t smem_u32(const void* p) {
    uint32_t a;
    asm("{ .reg .u64 t; cvta.to.shared.u64 t, %1; cvt.u32.u64 %0, t; }"
        : "=r"(a) : "l"(p));
    return a;
}
#define CP16(dst, src) \
    asm volatile("cp.async.cg.shared.global [%0], [%1], 16;" \
                 :: "r"(dst), "l"(src) : "memory")
#define CP_COMMIT() asm volatile("cp.async.commit_group;" ::: "memory")
#define CP_WAIT1()  asm volatile("cp.async.wait_group 1;"  ::: "memory")

__device__ __forceinline__ void ldsm4(uint32_t* r, uint32_t addr) {
    asm volatile("ldmatrix.sync.aligned.m8n8.x4.shared.b16 {%0,%1,%2,%3}, [%4];"
                 : "=r"(r[0]), "=r"(r[1]), "=r"(r[2]), "=r"(r[3]) : "r"(addr));
}
__device__ __forceinline__ void mma16816(float* d, const uint32_t* a,
                                         uint32_t b0, uint32_t b1) {
    asm volatile(
        "mma.sync.aligned.m16n8k16.row.col.f32.bf16.bf16.f32 "
        "{%0,%1,%2,%3}, {%4,%5,%6,%7}, {%8,%9}, {%0,%1,%2,%3};"
        : "+f"(d[0]), "+f"(d[1]), "+f"(d[2]), "+f"(d[3])
        : "r"(a[0]), "r"(a[1]), "r"(a[2]), "r"(a[3]), "r"(b0), "r"(b1));
}

__device__ __forceinline__ void split4(float4 v, uint2& hh, uint2& ll) {
    __nv_bfloat162 h0 = __floats2bfloat162_rn(v.x, v.y);
    __nv_bfloat162 h1 = __floats2bfloat162_rn(v.z, v.w);
    float2 f0 = __bfloat1622float2(h0);
    float2 f1 = __bfloat1622float2(h1);
    __nv_bfloat162 l0 = __floats2bfloat162_rn(v.x - f0.x, v.y - f0.y);
    __nv_bfloat162 l1 = __floats2bfloat162_rn(v.z - f1.x, v.w - f1.y);
    hh.x = *(uint32_t*)&h0; hh.y = *(uint32_t*)&h1;
    ll.x = *(uint32_t*)&l0; ll.y = *(uint32_t*)&l1;
}
__device__ __forceinline__ void split2(float x, float y, uint32_t& h2, uint32_t& l2) {
    __nv_bfloat162 h = __floats2bfloat162_rn(x, y);
    float2 f = __bfloat1622float2(h);
    __nv_bfloat162 l = __floats2bfloat162_rn(x - f.x, y - f.y);
    h2 = *(uint32_t*)&h; l2 = *(uint32_t*)&l;
}

// ---------------- elementwise fp32 -> (hi,lo) bf16 ----------------
__global__ __launch_bounds__(256)
void split_kernel(const float* __restrict__ in, __nv_bfloat16* __restrict__ hi,
                  __nv_bfloat16* __restrict__ lo, int n4)
{
    int i = blockIdx.x * 256 + threadIdx.x;
    if (i < n4) {
        float4 v = ((const float4*)in)[i];
        uint2 hh, ll; split4(v, hh, ll);
        ((uint2*)hi)[i] = hh;
        ((uint2*)lo)[i] = ll;
    }
}

// ---------------- GEMM: C[128x128 tile] = alpha * A @ B^T ------------------
// A,B given as (hi,lo) bf16 [rows][K]; smem stage layout per matrix:
// 128 rows x (hi 32 | lo 32 | pad 8) bf16, row stride 144B (conflict-free).
template<bool SPLIT_OUT>
__global__ void __launch_bounds__(256, 2)
gemm_async(const __nv_bfloat16* __restrict__ Ah, const __nv_bfloat16* __restrict__ Al,
           const __nv_bfloat16* __restrict__ Bh, const __nv_bfloat16* __restrict__ Bl,
           float* __restrict__ C, __nv_bfloat16* __restrict__ Ch,
           __nv_bfloat16* __restrict__ Cl, const float* __restrict__ bias,
           int K, int lda, int ldb, int ldc, int zdiv,
           long long sA1, long long sA2, long long sB1, long long sB2,
           long long sC1, long long sC2, float alpha)
{
    extern __shared__ __align__(16) char smem[];
    const uint32_t sb = smem_u32(smem);

    const int tid  = threadIdx.x;
    const int lane = tid & 31;
    const int wid  = tid >> 5;
    const int wm   = (wid & 1) * 64;
    const int wn   = (wid >> 1) * 32;

    const int z = blockIdx.z;
    const int zq = z / zdiv, zr = z - zq * zdiv;
    const __nv_bfloat16* Ahp = Ah + zq * sA1 + zr * sA2 + (long long)blockIdx.y * 128 * lda;
    const __nv_bfloat16* Alp = Al + zq * sA1 + zr * sA2 + (long long)blockIdx.y * 128 * lda;
    const __nv_bfloat16* Bhp = Bh + zq * sB1 + zr * sB2 + (long long)blockIdx.x * 128 * ldb;
    const __nv_bfloat16* Blp = Bl + zq * sB1 + zr * sB2 + (long long)blockIdx.x * 128 * ldb;

    float d[4][4][4];
#pragma unroll
    for (int i = 0; i < 4; i++)
#pragma unroll
        for (int j = 0; j < 4; j++)
#pragma unroll
            for (int e = 0; e < 4; e++) d[i][j][e] = 0.f;

    auto issue = [&](int c, int s) {
        const uint32_t base = sb + s * STAGE_BYTES;
#pragma unroll
        for (int i = 0; i < 4; i++) {
            int g = i * 256 + tid;
            int row = g >> 3, part = (g >> 2) & 1, j = g & 3;
            const __nv_bfloat16* src =
                (part ? Alp : Ahp) + (long long)row * lda + c * 32 + j * 8;
            CP16(base + (row * SA + part * 32 + j * 8) * 2, src);
        }
#pragma unroll
        for (int i = 0; i < 4; i++) {
            int g = i * 256 + tid;
            int row = g >> 3, part = (g >> 2) & 1, j = g & 3;
            const __nv_bfloat16* src =
                (part ? Blp : Bhp) + (long long)row * ldb + c * 32 + j * 8;
            CP16(base + MAT_BYTES + (row * SA + part * 32 + j * 8) * 2, src);
        }
    };

    const int nch = K >> 5;     // 32 fp32-K per chunk
    issue(0, 0); CP_COMMIT();
    if (nch > 1) issue(1, 1);
    CP_COMMIT();

    for (int c = 0; c < nch; ++c) {
        CP_WAIT1();
        __syncthreads();
        const int cn = c + 2;
        if (cn < nch) issue(cn, cn % 3);
        CP_COMMIT();

        const uint32_t a_base = sb + (c % 3) * STAGE_BYTES;
        const uint32_t b_base = a_base + MAT_BYTES;
#pragma unroll
        for (int ksp = 0; ksp < 2; ksp++) {
            uint32_t ah[4][4], al[4][4], bh[4][2], bl[4][2];
#pragma unroll
            for (int mi = 0; mi < 4; mi++) {
                uint32_t addr = a_base +
                    ((wm + mi * 16 + (lane & 15)) * SA + ksp * 16 + (lane >> 4) * 8) * 2;
                ldsm4(ah[mi], addr);
                ldsm4(al[mi], addr + 64);      // +32 bf16 cols
            }
#pragma unroll
            for (int nb = 0; nb < 2; nb++) {
                uint32_t r[4];
                uint32_t addr = b_base +
                    ((wn + nb * 16 + (lane & 15)) * SA + ksp * 16 + (lane >> 4) * 8) * 2;
                ldsm4(r, addr);
                bh[nb * 2][0] = r[0]; bh[nb * 2][1] = r[2];
                bh[nb * 2 + 1][0] = r[1]; bh[nb * 2 + 1][1] = r[3];
                ldsm4(r, addr + 64);
                bl[nb * 2][0] = r[0]; bl[nb * 2][1] = r[2];
                bl[nb * 2 + 1][0] = r[1]; bl[nb * 2 + 1][1] = r[3];
            }
#pragma unroll
            for (int mi = 0; mi < 4; mi++)
#pragma unroll
                for (int ni = 0; ni < 4; ni++) {
                    mma16816(d[mi][ni], ah[mi], bh[ni][0], bh[ni][1]);
                    mma16816(d[mi][ni], ah[mi], bl[ni][0], bl[ni][1]);
                    mma16816(d[mi][ni], al[mi], bh[ni][0], bh[ni][1]);
                }
        }
    }

    // ---- epilogue ----
    const int r0 = lane >> 2;
    const int c0 = (lane & 3) << 1;
    if (!SPLIT_OUT) {
        float* Cp = C + zq * sC1 + zr * sC2
                      + (long long)blockIdx.y * 128 * ldc + blockIdx.x * 128;
#pragma unroll
        for (int mi = 0; mi < 4; mi++)
#pragma unroll
            for (int ni = 0; ni < 4; ni++) {
                int row = wm + mi * 16 + r0;
                int col = wn + ni * 8 + c0;
                float2 v0, v1;
                v0.x = d[mi][ni][0] * alpha; v0.y = d[mi][ni][1] * alpha;
                v1.x = d[mi][ni][2] * alpha; v1.y = d[mi][ni][3] * alpha;
                if (bias) {
                    int gc = blockIdx.x * 128 + col;
                    float b0 = bias[gc], b1 = bias[gc + 1];
                    v0.x += b0; v0.y += b1; v1.x += b0; v1.y += b1;
                }
                *(float2*)(Cp + (long long)row * ldc + col)       = v0;
                *(float2*)(Cp + (long long)(row + 8) * ldc + col) = v1;
            }
    } else {
        const long long coff = zq * sC1 + zr * sC2
                             + (long long)blockIdx.y * 128 * ldc + blockIdx.x * 128;
        __nv_bfloat16* Chp = Ch + coff;
        __nv_bfloat16* Clp = Cl + coff;
#pragma unroll
        for (int mi = 0; mi < 4; mi++)
#pragma unroll
            for (int ni = 0; ni < 4; ni++) {
                int row = wm + mi * 16 + r0;
                int col = wn + ni * 8 + c0;
                uint32_t h2, l2;
                split2(d[mi][ni][0] * alpha, d[mi][ni][1] * alpha, h2, l2);
                *(uint32_t*)(Chp + (long long)row * ldc + col) = h2;
                *(uint32_t*)(Clp + (long long)row * ldc + col) = l2;
                split2(d[mi][ni][2] * alpha, d[mi][ni][3] * alpha, h2, l2);
                *(uint32_t*)(Chp + (long long)(row + 8) * ldc + col) = h2;
                *(uint32_t*)(Clp + (long long)(row + 8) * ldc + col) = l2;
            }
    }
}

// ---------------- softmax over rows of S[*,2048]; writes split P -----------
__global__ __launch_bounds__(256)
void softmax_kernel(const float* __restrict__ S,
                    __nv_bfloat16* __restrict__ Ph, __nv_bfloat16* __restrict__ Pl)
{
    const int T = 2048;
    const float* row = S + (long long)blockIdx.x * T;
    const int tid = threadIdx.x;

    float4 v0 = *(const float4*)(row + tid * 8);
    float4 v1 = *(const float4*)(row + tid * 8 + 4);

    float m = fmaxf(fmaxf(fmaxf(v0.x, v0.y), fmaxf(v0.z, v0.w)),
                    fmaxf(fmaxf(v1.x, v1.y), fmaxf(v1.z, v1.w)));
#pragma unroll
    for (int o = 16; o; o >>= 1) m = fmaxf(m, __shfl_xor_sync(0xffffffffu, m, o));

    __shared__ float red[8];
    if ((tid & 31) == 0) red[tid >> 5] = m;
    __syncthreads();
    m = red[0];
#pragma unroll
    for (int i = 1; i < 8; i++) m = fmaxf(m, red[i]);

    v0.x = __expf(v0.x - m); v0.y = __expf(v0.y - m);
    v0.z = __expf(v0.z - m); v0.w = __expf(v0.w - m);
    v1.x = __expf(v1.x - m); v1.y = __expf(v1.y - m);
    v1.z = __expf(v1.z - m); v1.w = __expf(v1.w - m);

    float s = v0.x + v0.y + v0.z + v0.w + v1.x + v1.y + v1.z + v1.w;
#pragma unroll
    for (int o = 16; o; o >>= 1) s += __shfl_xor_sync(0xffffffffu, s, o);

    __syncthreads();
    if ((tid & 31) == 0) red[tid >> 5] = s;
    __syncthreads();
    s = red[0];
#pragma unroll
    for (int i = 1; i < 8; i++) s += red[i];

    const float inv = 1.f / s;
    v0.x *= inv; v0.y *= inv; v0.z *= inv; v0.w *= inv;
    v1.x *= inv; v1.y *= inv; v1.z *= inv; v1.w *= inv;

    uint2 hh0, ll0, hh1, ll1;
    split4(v0, hh0, ll0);
    split4(v1, hh1, ll1);
    uint4 hv; hv.x = hh0.x; hv.y = hh0.y; hv.z = hh1.x; hv.w = hh1.y;
    uint4 lv; lv.x = ll0.x; lv.y = ll0.y; lv.z = ll1.x; lv.w = ll1.y;
    ((uint4*)(Ph + (long long)blockIdx.x * T))[tid] = hv;
    ((uint4*)(Pl + (long long)blockIdx.x * T))[tid] = lv;
}

// ---------------- V transpose (split): vt[z][c][t] = V[b,t,h,c] ------------
__global__ __launch_bounds__(256)
void transpose_v_kernel(const __nv_bfloat16* __restrict__ qh,
                        const __nv_bfloat16* __restrict__ ql,
                        __nv_bfloat16* __restrict__ vh,
                        __nv_bfloat16* __restrict__ vl)
{
    __shared__ __nv_bfloat16 th[32][33], tl[32][33];
    const int tx = threadIdx.x & 31, ty = threadIdx.x >> 5;
    const int z = blockIdx.z, b = z >> 2, h = z & 3;
    const long long srcbase = (long long)b * 2048 * 6144 + 4096 + h * 512;
    const int k0 = blockIdx.x << 5, c0 = blockIdx.y << 5;
#pragma unroll
    for (int i = 0; i < 4; i++) {
        long long s = srcbase + (long long)(k0 + ty + i * 8) * 6144 + c0 + tx;
        th[ty + i * 8][tx] = qh[s];
        tl[ty + i * 8][tx] = ql[s];
    }
    __syncthreads();
    const long long dstbase = (long long)z * 512 * 2048;
#pragma unroll
    for (int i = 0; i < 4; i++) {
        long long dd = dstbase + (long long)(c0 + ty + i * 8) * 2048 + k0 + tx;
        vh[dd] = th[tx][ty + i * 8];
        vl[dd] = tl[tx][ty + i * 8];
    }
}

// ---------------------------------------------------------------------------
extern "C" void kernel_launch(void* const* d_in, const int* in_sizes, int n_in,
                              void* d_out, int out_size)
{
    const float* x      = (const float*)d_in[0];   // [8,2048,512]
    const float* qkv_w  = (const float*)d_in[1];   // [6144,512]
    const float* proj_w = (const float*)d_in[2];   // [512,2048]
    const float* proj_b = (const float*)d_in[3];   // [512]
    float* out = (float*)d_out;                    // [8,2048,512]

    float* attn;
    __nv_bfloat16 *qh, *qlo, *ph, *pl, *vth, *vtl, *aoh, *aol;
    __nv_bfloat16 *xh, *xl, *w1h, *w1l, *w2h, *w2l;
    cudaGetSymbolAddress((void**)&attn, g_attn);
    cudaGetSymbolAddress((void**)&qh,  g_qkv_hi);  cudaGetSymbolAddress((void**)&qlo, g_qkv_lo);
    cudaGetSymbolAddress((void**)&ph,  g_p_hi);    cudaGetSymbolAddress((void**)&pl,  g_p_lo);
    cudaGetSymbolAddress((void**)&vth, g_vt_hi);   cudaGetSymbolAddress((void**)&vtl, g_vt_lo);
    cudaGetSymbolAddress((void**)&aoh, g_ao_hi);   cudaGetSymbolAddress((void**)&aol, g_ao_lo);
    cudaGetSymbolAddress((void**)&xh,  g_x_hi);    cudaGetSymbolAddress((void**)&xl,  g_x_lo);
    cudaGetSymbolAddress((void**)&w1h, g_w1_hi);   cudaGetSymbolAddress((void**)&w1l, g_w1_lo);
    cudaGetSymbolAddress((void**)&w2h, g_w2_hi);   cudaGetSymbolAddress((void**)&w2l, g_w2_lo);

    cudaFuncSetAttribute(gemm_async<false>,
                         cudaFuncAttributeMaxDynamicSharedMemorySize, SMEM_TOTAL);
    cudaFuncSetAttribute(gemm_async<true>,
                         cudaFuncAttributeMaxDynamicSharedMemorySize, SMEM_TOTAL);

    const int T = 2048;
    const float scale = 0.088388347648318447f;   // (512/4)^-0.5
    const long long TT = (long long)T * T;

    // 0) pre-split inputs
    split_kernel<<<8192, 256>>>(x,      xh,  xl,  2097152);
    split_kernel<<<3072, 256>>>(qkv_w,  w1h, w1l,  786432);
    split_kernel<<<1024, 256>>>(proj_w, w2h, w2l,  262144);

    // 1) qkv = x @ qkv_w^T  -> split qkv
    {
        dim3 grid(48, 128, 1);
        gemm_async<true><<<grid, 256, SMEM_TOTAL>>>(
            xh, xl, w1h, w1l, nullptr, qh, qlo, nullptr,
            512, 512, 512, 6144, 1,
            0, 0, 0, 0, 0, 0, 1.0f);
    }
    // 1b) vt split
    {
        dim3 grid(64, 16, 32);
        transpose_v_kernel<<<grid, 256>>>(qh, qlo, vth, vtl);
    }
    // 2) S = scale * Q K^T  (fp32 out)
    {
        dim3 grid(16, 16, 32);
        gemm_async<false><<<grid, 256, SMEM_TOTAL>>>(
            qh, qlo, qh + 2048, qlo + 2048, attn, nullptr, nullptr, nullptr,
            512, 6144, 6144, T, 4,
            (long long)T * 6144, 512,
            (long long)T * 6144, 512,
            4 * TT, TT, scale);
    }
    // 3) softmax -> split P
    softmax_kernel<<<32 * T, 256>>>(attn, ph, pl);
    // 4) ao = P @ vt^T -> split ao  (packed [b*T+q][h*512+c])
    {
        dim3 grid(4, 16, 32);
        gemm_async<true><<<grid, 256, SMEM_TOTAL>>>(
            ph, pl, vth, vtl, nullptr, aoh, aol, nullptr,
            T, T, T, T, 4,
            4 * TT, TT,
            (long long)4 * 512 * T, (long long)512 * T,
            TT, 512, 1.0f);
    }
    // 5) out = ao @ proj_w^T + proj_b  (fp32 out)
    {
        dim3 grid(4, 128, 1);
        gemm_async<false><<<grid, 256, SMEM_TOTAL>>>(
            aoh, aol, w2h, w2l, out, nullptr, nullptr, proj_b,
            T, T, T, 512, 1,
            0, 0, 0, 0, 0, 0, 1.0f);
    }
}